// round 9
// baseline (speedup 1.0000x reference)
#include <cuda_runtime.h>
#include <cuda_fp16.h>
#include <math.h>

#define IN_DIM 128
#define OUT_DIM 128
#define BATCH 1024
#define WARPS 8         // warps per block, each owns its own b stream
#define BB 8            // batches per warp

// out layout (concatenated reference tuple):
//   y_out      : [0, 131072)
//   preacts    : [131072, +16777216)
//   postacts   : next 16777216
//   postspline : next 16777216

__global__ __launch_bounds__(256) void kan_kernel(
    const float* __restrict__ x,
    const float* __restrict__ grid,
    const float* __restrict__ coef,
    const float* __restrict__ scale_base,
    const float* __restrict__ scale_sp,
    const float* __restrict__ mask,
    float* __restrict__ out)
{
    const int lane = threadIdx.x & 31;
    const int warp = threadIdx.x >> 5;          // 0..7
    const int j    = blockIdx.x;                // output-dim index
    const int sb   = j * IN_DIM;
    const int i0   = lane << 2;                 // this thread covers i0..i0+3

    // per-interval cubic polynomial table, fp16-packed:
    // ctabh[i][qc] = uint2{ half2(A,B), half2(C,D) } for interval qc-1.
    // qc=0 / qc=12 are zero polys (outside spline support).
    __shared__ uint2 ctabh[128][13];

    if (threadIdx.x < 128) {
        const int i = threadIdx.x;
        const float4 c0 = *(const float4*)&coef[(size_t)(sb + i) * 8 + 0];
        const float4 c1 = *(const float4*)&coef[(size_t)(sb + i) * 8 + 4];
        float cm[8] = {c0.x, c0.y, c0.z, c0.w, c1.x, c1.y, c1.z, c1.w};

        ctabh[i][0]  = make_uint2(0u, 0u);
        ctabh[i][12] = make_uint2(0u, 0u);
        #pragma unroll
        for (int q = 0; q < 11; q++) {
            const int m0 = q - 3;
            float k0 = (m0 + 0 >= 0 && m0 + 0 <= 7) ? cm[m0 + 0] : 0.0f;
            float k1 = (m0 + 1 >= 0 && m0 + 1 <= 7) ? cm[m0 + 1] : 0.0f;
            float k2 = (m0 + 2 >= 0 && m0 + 2 <= 7) ? cm[m0 + 2] : 0.0f;
            float k3 = (m0 + 3 >= 0 && m0 + 3 <= 7) ? cm[m0 + 3] : 0.0f;
            float A  = (k0 + 4.0f * k1 + k2) * (1.0f / 6.0f);
            float Bc = (k2 - k0) * 0.5f;
            float Cc = (k0 - 2.0f * k1 + k2) * 0.5f;
            float D  = (k3 - k0) * (1.0f / 6.0f) + (k1 - k2) * 0.5f;
            __half2 ab = __floats2half2_rn(A, Bc);
            __half2 cd = __floats2half2_rn(Cc, D);
            ctabh[i][q + 1] = make_uint2(*(unsigned*)&ab, *(unsigned*)&cd);
        }
    }

    // per-element loop-invariant setup; element r of this thread is i = 4*lane + r
    float poff[4], invh[4], msb[4], mssp[4];
    #pragma unroll
    for (int r = 0; r < 4; r++) {
        const int s = sb + i0 + r;
        float g0 = grid[s * 6 + 0];
        float g5 = grid[s * 6 + 5];
        float h  = (g5 - g0) * 0.2f;
        float e0 = g0 - h; e0 -= h; e0 -= h;    // match reference's sequential extension
        float ih = 1.0f / h;
        invh[r] = ih;
        poff[r] = -e0 * ih;                      // pos = t*ih + poff
        float mv = mask[s];
        msb[r]  = mv * scale_base[s];
        mssp[r] = mv * scale_sp[s];
    }

    __syncthreads();   // ctabh ready; the ONLY block barrier

    float* y_out      = out;
    float* preacts    = out + 131072;
    float* postacts   = preacts + 16777216;
    float* postspline = postacts + 16777216;

    const int b_start = blockIdx.y * (WARPS * BB) + warp * BB;

    float4 tn = *(const float4*)&x[b_start * IN_DIM + i0];   // prefetch

    #pragma unroll 2
    for (int bb = 0; bb < BB; bb++) {
        const int b = b_start + bb;
        const float4 t4 = tn;
        if (bb + 1 < BB)
            tn = *(const float4*)&x[(b + 1) * IN_DIM + i0];

        float t[4] = {t4.x, t4.y, t4.z, t4.w};
        float y[4], spl[4];

        #pragma unroll
        for (int r = 0; r < 4; r++) {
            const int i = i0 + r;

            // silu via MUFU (fast exp + fast divide)
            float base = __fdividef(t[r], 1.0f + __expf(-t[r]));

            // spline via per-interval cubic (Horner), fp16 table
            float pos = fmaf(t[r], invh[r], poff[r]);
            float qf  = floorf(pos);
            float u   = pos - qf;
            int   qc  = min(max((int)qf, -1), 11) + 1;   // 0..12

            const uint2 e = ctabh[i][qc];
            float2 ab = __half22float2(*(const __half2*)&e.x);
            float2 cd = __half22float2(*(const __half2*)&e.y);
            float sp = fmaf(fmaf(fmaf(cd.y, u, cd.x), u, ab.y), u, ab.x);

            spl[r] = sp;
            y[r]   = fmaf(msb[r], base, mssp[r] * sp);
        }

        const size_t idx = ((size_t)b * OUT_DIM + j) * IN_DIM + i0;

        // default write-back stores: let the output stay dirty-resident in L2
        // across graph replays (202MB output vs ~126MB L2 -> large write-hit share)
        *(float4*)&preacts[idx]    = t4;
        *(float4*)&postacts[idx]   = make_float4(y[0], y[1], y[2], y[3]);
        *(float4*)&postspline[idx] = make_float4(spl[0], spl[1], spl[2], spl[3]);

        // y_out[b, j] = sum over all 128 i — pure warp reduction
        float v = (y[0] + y[1]) + (y[2] + y[3]);
        #pragma unroll
        for (int o = 16; o; o >>= 1) v += __shfl_xor_sync(0xffffffffu, v, o);
        if (lane == 0) y_out[(size_t)b * OUT_DIM + j] = v;
    }
}

extern "C" void kernel_launch(void* const* d_in, const int* in_sizes, int n_in,
                              void* d_out, int out_size) {
    const float* x          = (const float*)d_in[0];
    const float* grid       = (const float*)d_in[1];
    const float* coef       = (const float*)d_in[2];
    const float* scale_base = (const float*)d_in[3];
    const float* scale_sp   = (const float*)d_in[4];
    const float* mask       = (const float*)d_in[5];
    float* out = (float*)d_out;

    dim3 gridDim(OUT_DIM, BATCH / (WARPS * BB));   // (128, 16) = 2048 blocks
    dim3 blockDim(256);
    kan_kernel<<<gridDim, blockDim>>>(x, grid, coef, scale_base, scale_sp, mask, out);
}